// round 2
// baseline (speedup 1.0000x reference)
#include <cuda_runtime.h>
#include <math.h>

#define Bn 2
#define Ll 16384
#define Cc 64
#define DI 128
#define Kk 4
#define NSt 16
#define NB 4

// -------------------- scratch (device globals; no allocation) --------------------
__device__ float g_t  [Bn*Ll*Cc];       // residual stream (b,l,64)
__device__ float g_h  [Bn*Ll*Cc];       // LN scratch (b,l,64)
__device__ float g_xz [Bn*Ll*256];      // in_proj out / MLP hidden (b,l,256)
__device__ float g_xc [Bn*DI*Ll];       // conv+silu out (b,d,l)
__device__ float g_u1 [Bn*DI*Ll];       // transposed xc (b,d,l') l'=w*H+h
__device__ float g_bc [Bn*Kk*Ll*32];    // B(16)+C(16) per (b,k,l)
__device__ float g_delta[16777216];     // (b,k,d,l)
__device__ float g_ys   [16777216];     // (b,k,d,l)
__device__ float g_ym [Bn*DI*Ll];       // merged (b,d,l)
__device__ float g_yo [Bn*Ll*DI];       // gated+LN (b,l,d)
__device__ float g_o1 [Bn*32*Ll];       // head conv1 out (b,32,l)

__device__ __forceinline__ float geluf(float v){
    return 0.5f*v*(1.f + erff(v*0.70710678118654752f));
}

// -------------------- stem: f = 1x1 conv over concat(x,y) --------------------
__global__ void k_reduce(const float* __restrict__ x, const float* __restrict__ y,
                         const float* __restrict__ rw, float* __restrict__ f){
    __shared__ float sx[128][33];
    __shared__ float so[64][33];
    int b = blockIdx.y; int l0 = blockIdx.x*32;
    int tid = threadIdx.x;
    for (int e = tid; e < 128*32; e += 256){
        int c = e>>5, li = e&31;
        sx[c][li] = (c < 64) ? x[((size_t)(b*64+c))*Ll + l0+li]
                             : y[((size_t)(b*64+c-64))*Ll + l0+li];
    }
    __syncthreads();
    int o = tid>>2, lb = (tid&3)*8;
    float acc[8] = {0.f,0.f,0.f,0.f,0.f,0.f,0.f,0.f};
    for (int c = 0; c < 128; c++){
        float w = __ldg(rw + o*128 + c);
        #pragma unroll
        for (int j = 0; j < 8; j++) acc[j] += w*sx[c][lb+j];
    }
    #pragma unroll
    for (int j = 0; j < 8; j++) so[o][lb+j] = acc[j];
    __syncthreads();
    for (int e = tid; e < 64*32; e += 256){
        int oo = e>>5, li = e&31;
        f[((size_t)(b*64+oo))*Ll + l0+li] = so[oo][li];
    }
}

// -------------------- patch embed 1x1 conv (reads f), writes (b,l,64) --------------------
__global__ void k_patch(const float* __restrict__ f, const float* __restrict__ pw,
                        float* __restrict__ out){
    __shared__ float sx[64][33];
    __shared__ float so[64][33];
    int b = blockIdx.y; int l0 = blockIdx.x*32;
    int tid = threadIdx.x;
    for (int e = tid; e < 64*32; e += 256){
        int c = e>>5, li = e&31;
        sx[c][li] = f[((size_t)(b*64+c))*Ll + l0+li];
    }
    __syncthreads();
    int o = tid>>2, lb = (tid&3)*8;
    float acc[8] = {0.f,0.f,0.f,0.f,0.f,0.f,0.f,0.f};
    for (int c = 0; c < 64; c++){
        float w = __ldg(pw + o*64 + c);
        #pragma unroll
        for (int j = 0; j < 8; j++) acc[j] += w*sx[c][lb+j];
    }
    #pragma unroll
    for (int j = 0; j < 8; j++) so[o][lb+j] = acc[j];
    __syncthreads();
    for (int e = tid; e < 64*32; e += 256){
        int o2 = e&63, li = e>>6;
        out[((size_t)(b*Ll) + l0 + li)*64 + o2] = so[o2][li];
    }
}

// -------------------- LayerNorm over last dim of 64 --------------------
__global__ void k_ln64(const float* __restrict__ in, float* __restrict__ out,
                       const float* __restrict__ g, const float* __restrict__ bb){
    int row = blockIdx.x; int t = threadIdx.x;
    float v = in[(size_t)row*64 + t];
    float s = v, s2 = v*v;
    #pragma unroll
    for (int o = 16; o; o >>= 1){ s += __shfl_xor_sync(~0u, s, o); s2 += __shfl_xor_sync(~0u, s2, o); }
    __shared__ float sh[4];
    if ((t&31) == 0){ sh[t>>5] = s; sh[2+(t>>5)] = s2; }
    __syncthreads();
    float mean = (sh[0]+sh[1])*(1.f/64.f);
    float m2   = (sh[2]+sh[3])*(1.f/64.f);
    float rstd = rsqrtf(m2 - mean*mean + 1e-5f);
    out[(size_t)row*64 + t] = (v-mean)*rstd*g[t] + bb[t];
}

// -------------------- generic tiled GEMM: C[M,N] (+)= act(A[M,K] @ W[N,K]^T + bias) ------
__global__ void k_gemm(const float* __restrict__ A, const float* __restrict__ Wm,
                       const float* __restrict__ bias, float* __restrict__ C,
                       int M, int Nq, int Kd, int act, int accum){
    __shared__ float As[16][68];
    __shared__ float Ws[16][68];
    int m0 = blockIdx.y<<6, n0 = blockIdx.x<<6;
    int tid = threadIdx.x;
    int tm = tid>>4, tn = tid&15;
    int lr = tid>>2, lc = (tid&3)<<2;
    float acc[4][4] = {};
    for (int kk = 0; kk < Kd; kk += 16){
        float4 av = *(const float4*)(A  + (size_t)(m0+lr)*Kd + kk + lc);
        float4 wv = *(const float4*)(Wm + (size_t)(n0+lr)*Kd + kk + lc);
        As[lc+0][lr]=av.x; As[lc+1][lr]=av.y; As[lc+2][lr]=av.z; As[lc+3][lr]=av.w;
        Ws[lc+0][lr]=wv.x; Ws[lc+1][lr]=wv.y; Ws[lc+2][lr]=wv.z; Ws[lc+3][lr]=wv.w;
        __syncthreads();
        #pragma unroll
        for (int k = 0; k < 16; k++){
            float a0=As[k][tm*4+0], a1=As[k][tm*4+1], a2=As[k][tm*4+2], a3=As[k][tm*4+3];
            float w0=Ws[k][tn*4+0], w1=Ws[k][tn*4+1], w2=Ws[k][tn*4+2], w3=Ws[k][tn*4+3];
            acc[0][0]+=a0*w0; acc[0][1]+=a0*w1; acc[0][2]+=a0*w2; acc[0][3]+=a0*w3;
            acc[1][0]+=a1*w0; acc[1][1]+=a1*w1; acc[1][2]+=a1*w2; acc[1][3]+=a1*w3;
            acc[2][0]+=a2*w0; acc[2][1]+=a2*w1; acc[2][2]+=a2*w2; acc[2][3]+=a2*w3;
            acc[3][0]+=a3*w0; acc[3][1]+=a3*w1; acc[3][2]+=a3*w2; acc[3][3]+=a3*w3;
        }
        __syncthreads();
    }
    float bv[4] = {0.f,0.f,0.f,0.f};
    if (bias){
        #pragma unroll
        for (int j = 0; j < 4; j++) bv[j] = bias[n0 + tn*4 + j];
    }
    #pragma unroll
    for (int i2 = 0; i2 < 4; i2++){
        int m = m0 + tm*4 + i2;
        float4* p = (float4*)(C + (size_t)m*Nq + n0 + tn*4);
        float v0 = acc[i2][0]+bv[0], v1 = acc[i2][1]+bv[1], v2 = acc[i2][2]+bv[2], v3 = acc[i2][3]+bv[3];
        if (act == 1){ v0=geluf(v0); v1=geluf(v1); v2=geluf(v2); v3=geluf(v3); }
        float4 ov;
        if (accum){ float4 old = *p; ov.x=old.x+v0; ov.y=old.y+v1; ov.z=old.z+v2; ov.w=old.w+v3; }
        else      { ov.x=v0; ov.y=v1; ov.z=v2; ov.w=v3; }
        *p = ov;
    }
}

// -------------------- depthwise 3x3 conv + bias + SiLU: (b,l,256)[:128] -> (b,d,l) -------
__global__ void k_dwconv(const float* __restrict__ xz, const float* __restrict__ cw,
                         const float* __restrict__ cb, float* __restrict__ xc){
    int b = blockIdx.z, h = blockIdx.y, w0 = blockIdx.x<<5;
    int d = threadIdx.x;
    float wt[9];
    #pragma unroll
    for (int t2 = 0; t2 < 9; t2++) wt[t2] = __ldg(cw + d*9 + t2);
    float bi = __ldg(cb + d);
    __shared__ float s[32][133];
    for (int w = 0; w < 32; w++){
        float acc = bi;
        #pragma unroll
        for (int kh = 0; kh < 3; kh++){
            int hh = h + kh - 1;
            if ((unsigned)hh < 128u){
                #pragma unroll
                for (int kw = 0; kw < 3; kw++){
                    int ww = w0 + w + kw - 1;
                    if ((unsigned)ww < 128u)
                        acc += wt[kh*3+kw]*__ldg(xz + ((size_t)(b*Ll + hh*128 + ww))*256 + d);
                }
            }
        }
        acc = acc/(1.f + expf(-acc));   // SiLU
        s[w][d] = acc;
    }
    __syncthreads();
    for (int e = d; e < 4096; e += 128){
        int dd = e>>5, w = e&31;
        xc[((size_t)(b*128+dd))*Ll + h*128 + w0 + w] = s[w][dd];
    }
}

// -------------------- per-channel HxW transpose (for wh scan order) --------------------
__global__ void k_transp(const float* __restrict__ src, float* __restrict__ dst){
    __shared__ float ts[32][33];
    int ch = blockIdx.z;
    int x0 = blockIdx.x<<5, y0 = blockIdx.y<<5;
    const float* s = src + (size_t)ch*Ll;
    float* d = dst + (size_t)ch*Ll;
    int x = threadIdx.x, ys0 = threadIdx.y;
    for (int yy = ys0; yy < 32; yy += 8) ts[yy][x] = s[(y0+yy)*128 + x0 + x];
    __syncthreads();
    for (int yy = ys0; yy < 32; yy += 8) d[(x0+yy)*128 + y0 + x] = ts[x][yy];
}

// -------------------- x_proj + dt_proj + softplus, produces BC and delta --------------------
__global__ void k_xproj(const float* __restrict__ xc, const float* __restrict__ u1,
                        const float* __restrict__ xpw, const float* __restrict__ dtw,
                        const float* __restrict__ dtb, float* __restrict__ bcbuf,
                        float* __restrict__ deltabuf){
    int k = blockIdx.y, b = blockIdx.z; int l0 = blockIdx.x*32;
    __shared__ float Us[128][33];
    __shared__ float Wp[36][128];
    __shared__ float xds[36][33];
    __shared__ float dtws[128][4];
    __shared__ float dtbs[128];
    int tid = threadIdx.x;
    const float* uptr = ((k&1) ? u1 : xc) + (size_t)b*128*Ll;
    bool rev = (k >= 2);
    for (int e = tid; e < 128*32; e += 256){
        int d = e>>5, lo = e&31;
        int pos = l0 + lo; int src = rev ? (Ll-1-pos) : pos;
        Us[d][lo] = uptr[(size_t)d*Ll + src];
    }
    for (int e = tid; e < 36*128; e += 256) Wp[e>>7][e&127] = xpw[(size_t)k*36*128 + e];
    for (int e = tid; e < 512; e += 256) dtws[e>>2][e&3] = dtw[(size_t)k*512 + e];
    if (tid < 128) dtbs[tid] = dtb[k*128 + tid];
    __syncthreads();
    for (int e = tid; e < 36*32; e += 256){
        int c = e>>5, lo = e&31;
        float acc = 0.f;
        #pragma unroll 8
        for (int d = 0; d < 128; d++) acc += Wp[c][d]*Us[d][lo];
        xds[c][lo] = acc;
    }
    __syncthreads();
    size_t bcbase = ((size_t)(b*4+k)*Ll + l0)*32;
    for (int e = tid; e < 32*32; e += 256){
        int lo = e>>5, n = e&31;
        bcbuf[bcbase + (size_t)lo*32 + n] = xds[4+n][lo];
    }
    size_t dbase = (size_t)(b*4+k)*128*Ll;
    for (int e = tid; e < 128*32; e += 256){
        int d = e>>5, lo = e&31;
        float v = dtbs[d];
        #pragma unroll
        for (int r = 0; r < 4; r++) v += dtws[d][r]*xds[r][lo];
        v = (v > 20.f) ? v : log1pf(expf(v));   // softplus
        deltabuf[dbase + (size_t)d*Ll + l0 + lo] = v;
    }
}

// -------------------- selective scan: one warp per (b,k,d), lane n = state n --------------------
__global__ void k_scan(const float* __restrict__ xc, const float* __restrict__ u1,
                       const float* __restrict__ delta, const float* __restrict__ bc,
                       const float* __restrict__ Alogs, const float* __restrict__ Ds,
                       float* __restrict__ ys){
    int wid = (blockIdx.x*blockDim.x + threadIdx.x) >> 5;
    int lane = threadIdx.x & 31;
    int d = wid & 127, k = (wid>>7)&3, b = wid>>9;
    const float* uptr = ((k&1) ? u1 : xc) + (size_t)(b*128 + d)*Ll;
    bool rev = (k >= 2);
    const float* dptr = delta + (size_t)((b*4+k)*128 + d)*Ll;
    const float* bcp  = bc + (size_t)(b*4+k)*Ll*32;
    float* yptr = ys + (size_t)((b*4+k)*128 + d)*Ll;
    float Aval = 0.f;
    if (lane < 16) Aval = -__expf(Alogs[(k*128+d)*16 + lane]);
    float Dval = Ds[k*128 + d];
    float h = 0.f;
    for (int c0 = 0; c0 < Ll; c0 += 32){
        float dv = dptr[c0 + lane];
        float uv = rev ? uptr[Ll-1-(c0+lane)] : uptr[c0 + lane];
        float yreg = 0.f;
        #pragma unroll 8
        for (int s = 0; s < 32; s++){
            float ds = __shfl_sync(~0u, dv, s);
            float us = __shfl_sync(~0u, uv, s);
            float bcv = bcp[(size_t)(c0+s)*32 + lane];
            float cn = __shfl_sync(~0u, bcv, lane + 16);
            float bnv = (lane < 16) ? bcv : 0.f;
            float a = __expf(ds*Aval);
            h = a*h + (ds*us)*bnv;
            float p = h*cn;
            p += __shfl_xor_sync(~0u, p, 16);
            p += __shfl_xor_sync(~0u, p, 8);
            p += __shfl_xor_sync(~0u, p, 4);
            p += __shfl_xor_sync(~0u, p, 2);
            p += __shfl_xor_sync(~0u, p, 1);
            if (lane == s) yreg = p + Dval*us;
        }
        yptr[c0 + lane] = yreg;
    }
}

// -------------------- cross-merge of the 4 scan directions --------------------
__global__ void k_merge(const float* __restrict__ ys, float* __restrict__ ym){
    int idx = blockIdx.x*256 + threadIdx.x;
    int l = idx & 16383;
    int d = (idx>>14) & 127;
    int b = idx>>21;
    int lT = ((l & 127) << 7) | (l >> 7);
    size_t cb = (size_t)((b*4)*128 + d)*Ll;
    size_t st = (size_t)128*Ll;
    float v = ys[cb + l]
            + ys[cb + 2*st + (Ll-1-l)]
            + ys[cb + 1*st + lT]
            + ys[cb + 3*st + (Ll-1-lT)];
    ym[((size_t)(b*128) + d)*Ll + l] = v;
}

// -------------------- out_norm(LN over 128) * silu(z), transpose to (b,l,d) --------------------
__global__ void k_yo(const float* __restrict__ ym, const float* __restrict__ xz,
                     const float* __restrict__ g, const float* __restrict__ bb,
                     float* __restrict__ yo){
    int l = blockIdx.x, b = blockIdx.y, d = threadIdx.x;
    float v = ym[((size_t)(b*128) + d)*Ll + l];
    float s = v, s2 = v*v;
    #pragma unroll
    for (int o = 16; o; o >>= 1){ s += __shfl_xor_sync(~0u, s, o); s2 += __shfl_xor_sync(~0u, s2, o); }
    __shared__ float sh[8];
    if ((d&31) == 0){ sh[d>>5] = s; sh[4+(d>>5)] = s2; }
    __syncthreads();
    float mean = (sh[0]+sh[1]+sh[2]+sh[3])*(1.f/128.f);
    float m2   = (sh[4]+sh[5]+sh[6]+sh[7])*(1.f/128.f);
    float rstd = rsqrtf(m2 - mean*mean + 1e-5f);
    float z = xz[((size_t)(b*Ll) + l)*256 + 128 + d];
    float sz = z/(1.f + expf(-z));
    yo[((size_t)(b*Ll) + l)*128 + d] = ((v-mean)*rstd*g[d] + bb[d])*sz;
}

// -------------------- head conv1: 64->32, 3x3, leaky --------------------
__global__ void k_conv1(const float* __restrict__ t, const float* __restrict__ w1,
                        float* __restrict__ o1){
    int b = blockIdx.z, h = blockIdx.y, w0 = blockIdx.x<<5;
    __shared__ float st[3*34*65];
    int tid = threadIdx.x;
    for (int e = tid; e < 3*34*64; e += 256){
        int c = e & 63;
        int wi = (e>>6) % 34;
        int r  = (e>>6) / 34;
        int hh = h + r - 1, ww = w0 + wi - 1;
        float v = 0.f;
        if ((unsigned)hh < 128u && (unsigned)ww < 128u)
            v = t[((size_t)(b*Ll) + hh*128 + ww)*64 + c];
        st[(r*34 + wi)*65 + c] = v;
    }
    __syncthreads();
    int w = tid & 31, og = tid>>5;
    float acc[4] = {0.f,0.f,0.f,0.f};
    for (int kh = 0; kh < 3; kh++)
        for (int kw = 0; kw < 3; kw++){
            const float* sp = st + (kh*34 + (w+kw))*65;
            for (int ic = 0; ic < 64; ic++){
                float v = sp[ic];
                #pragma unroll
                for (int j = 0; j < 4; j++)
                    acc[j] += __ldg(w1 + ((size_t)((og*4+j)*64 + ic))*9 + kh*3 + kw)*v;
            }
        }
    #pragma unroll
    for (int j = 0; j < 4; j++){
        float v = acc[j];
        v = (v >= 0.f) ? v : 0.01f*v;
        o1[((size_t)(b*32 + og*4 + j))*Ll + h*128 + w0 + w] = v;
    }
}

// -------------------- head conv2: 32->1, 3x3, + img, sigmoid --------------------
__global__ void k_conv2(const float* __restrict__ o1, const float* __restrict__ w2,
                        const float* __restrict__ img, float* __restrict__ out){
    int idx = blockIdx.x*256 + threadIdx.x;
    int b = idx>>14, l = idx & 16383, h = l>>7, w = l & 127;
    float acc = 0.f;
    for (int ic = 0; ic < 32; ic++){
        const float* base = o1 + (size_t)(b*32 + ic)*Ll;
        #pragma unroll
        for (int kh = 0; kh < 3; kh++){
            int hh = h + kh - 1; if ((unsigned)hh >= 128u) continue;
            #pragma unroll
            for (int kw = 0; kw < 3; kw++){
                int ww = w + kw - 1; if ((unsigned)ww >= 128u) continue;
                acc += __ldg(w2 + ic*9 + kh*3 + kw)*__ldg(base + hh*128 + ww);
            }
        }
    }
    float o = acc + img[idx];
    out[idx] = 1.f/(1.f + expf(-o));
}

// -------------------- launch --------------------
extern "C" void kernel_launch(void* const* d_in, const int* in_sizes, int n_in,
                              void* d_out, int out_size){
    const float* inp_img   = (const float*)d_in[0];
    const float* x         = (const float*)d_in[1];
    const float* y         = (const float*)d_in[2];
    const float* reduce_w  = (const float*)d_in[3];
    const float* patch_w   = (const float*)d_in[4];
    const float* patch_g   = (const float*)d_in[5];
    const float* patch_b   = (const float*)d_in[6];
    const float* ln1_g     = (const float*)d_in[7];
    const float* ln1_b     = (const float*)d_in[8];
    const float* in_proj_w = (const float*)d_in[9];
    const float* conv_w    = (const float*)d_in[10];
    const float* conv_b    = (const float*)d_in[11];
    const float* x_proj_w  = (const float*)d_in[12];
    const float* dt_proj_w = (const float*)d_in[13];
    const float* dt_proj_b = (const float*)d_in[14];
    const float* A_logs    = (const float*)d_in[15];
    const float* Ds_p      = (const float*)d_in[16];
    const float* out_norm_g= (const float*)d_in[17];
    const float* out_norm_b= (const float*)d_in[18];
    const float* out_proj_w= (const float*)d_in[19];
    const float* ln2_g     = (const float*)d_in[20];
    const float* ln2_b     = (const float*)d_in[21];
    const float* fc1_w     = (const float*)d_in[22];
    const float* fc1_b     = (const float*)d_in[23];
    const float* fc2_w     = (const float*)d_in[24];
    const float* fc2_b     = (const float*)d_in[25];
    const float* out1_w    = (const float*)d_in[26];
    const float* out2_w    = (const float*)d_in[27];

    float* out = (float*)d_out;
    float* f   = out + Bn*Ll;   // second output: f lives at offset 32768

    float *t, *h, *xz, *xc, *u1, *bcp, *delta, *ysb, *ymb, *yob, *o1b;
    cudaGetSymbolAddress((void**)&t,    g_t);
    cudaGetSymbolAddress((void**)&h,    g_h);
    cudaGetSymbolAddress((void**)&xz,   g_xz);
    cudaGetSymbolAddress((void**)&xc,   g_xc);
    cudaGetSymbolAddress((void**)&u1,   g_u1);
    cudaGetSymbolAddress((void**)&bcp,  g_bc);
    cudaGetSymbolAddress((void**)&delta,g_delta);
    cudaGetSymbolAddress((void**)&ysb,  g_ys);
    cudaGetSymbolAddress((void**)&ymb,  g_ym);
    cudaGetSymbolAddress((void**)&yob,  g_yo);
    cudaGetSymbolAddress((void**)&o1b,  g_o1);

    const int M = Bn*Ll;  // 32768

    k_reduce<<<dim3(512,2), 256>>>(x, y, reduce_w, f);
    k_patch <<<dim3(512,2), 256>>>(f, patch_w, h);
    k_ln64  <<<M, 64>>>(h, t, patch_g, patch_b);

    for (int i = 0; i < NB; i++){
        k_ln64  <<<M, 64>>>(t, h, ln1_g + i*64, ln1_b + i*64);
        k_gemm  <<<dim3(4,512), 256>>>(h, in_proj_w + (size_t)i*256*64, nullptr, xz,
                                       M, 256, 64, 0, 0);
        k_dwconv<<<dim3(4,128,2), 128>>>(xz, conv_w + (size_t)i*DI*9, conv_b + i*DI, xc);
        k_transp<<<dim3(4,4,Bn*DI), dim3(32,8)>>>(xc, u1);
        k_xproj <<<dim3(512,4,2), 256>>>(xc, u1,
                                         x_proj_w  + (size_t)i*Kk*36*DI,
                                         dt_proj_w + (size_t)i*Kk*DI*4,
                                         dt_proj_b + (size_t)i*Kk*DI,
                                         bcp, delta);
        k_scan  <<<128, 256>>>(xc, u1, delta, bcp,
                               A_logs + (size_t)i*Kk*DI*NSt,
                               Ds_p   + (size_t)i*Kk*DI, ysb);
        k_merge <<<16384, 256>>>(ysb, ymb);
        k_yo    <<<dim3(Ll,Bn), 128>>>(ymb, xz, out_norm_g + i*128, out_norm_b + i*128, yob);
        k_gemm  <<<dim3(1,512), 256>>>(yob, out_proj_w + (size_t)i*64*128, nullptr, t,
                                       M, 64, 128, 0, 1);
        k_ln64  <<<M, 64>>>(t, h, ln2_g + i*64, ln2_b + i*64);
        k_gemm  <<<dim3(4,512), 256>>>(h, fc1_w + (size_t)i*256*64, fc1_b + i*256, xz,
                                       M, 256, 64, 1, 0);
        k_gemm  <<<dim3(1,512), 256>>>(xz, fc2_w + (size_t)i*64*256, fc2_b + i*64, t,
                                       M, 64, 256, 0, 1);
    }

    k_conv1<<<dim3(4,128,2), 256>>>(t, out1_w, o1b);
    k_conv2<<<128, 256>>>(o1b, out2_w, inp_img, out);
}

// round 3
// speedup vs baseline: 5.4368x; 5.4368x over previous
#include <cuda_runtime.h>
#include <math.h>

#define Bn 2
#define Ll 16384
#define DI 128
#define Kk 4
#define NB 4
#define NC 128          // chunks per sequence
#define LC 128          // chunk length

// -------------------- scratch (device globals; no allocation) --------------------
__device__ float g_t  [Bn*Ll*64];        // residual stream (b,l,64)
__device__ float g_h  [Bn*Ll*64];        // LN scratch (b,l,64)
__device__ float g_xz [Bn*Ll*256];       // in_proj out / MLP hidden (b,l,256)
__device__ float g_xcT[Bn*Ll*DI];        // conv+silu out, NHWC (b,l,d)
__device__ float g_u1t[Bn*Ll*DI];        // wh-order (b, w*128+h, d)
__device__ float g_bc [Bn*Kk*Ll*32];     // B(16)+C(16) per (b,k,l)
__device__ float g_delta[Bn*Kk*Ll*DI];   // (b,k,l,d)
__device__ float g_ys   [(size_t)Bn*Kk*Ll*DI];   // (b,k,l,d)
__device__ float g_ym [Bn*Ll*DI];        // merged (b,l,d)
__device__ float g_yo [Bn*Ll*DI];        // gated+LN (b,l,d)
__device__ float g_o1 [Bn*32*Ll];        // head conv1 out (b,32,l)
__device__ float g_sum  [Bn*Kk*NC*DI*32];  // per-chunk {P[16], hEnd[16]}
__device__ float g_hinit[Bn*Kk*NC*DI*16];  // per-chunk init state

__device__ __forceinline__ float geluf(float v){
    return 0.5f*v*(1.f + erff(v*0.70710678118654752f));
}

// -------------------- stem: f = 1x1 conv over concat(x,y) --------------------
__global__ void k_reduce(const float* __restrict__ x, const float* __restrict__ y,
                         const float* __restrict__ rw, float* __restrict__ f){
    __shared__ float sx[128][33];
    __shared__ float so[64][33];
    int b = blockIdx.y; int l0 = blockIdx.x*32;
    int tid = threadIdx.x;
    for (int e = tid; e < 128*32; e += 256){
        int c = e>>5, li = e&31;
        sx[c][li] = (c < 64) ? x[((size_t)(b*64+c))*Ll + l0+li]
                             : y[((size_t)(b*64+c-64))*Ll + l0+li];
    }
    __syncthreads();
    int o = tid>>2, lb = (tid&3)*8;
    float acc[8] = {0.f,0.f,0.f,0.f,0.f,0.f,0.f,0.f};
    for (int c = 0; c < 128; c++){
        float w = __ldg(rw + o*128 + c);
        #pragma unroll
        for (int j = 0; j < 8; j++) acc[j] += w*sx[c][lb+j];
    }
    #pragma unroll
    for (int j = 0; j < 8; j++) so[o][lb+j] = acc[j];
    __syncthreads();
    for (int e = tid; e < 64*32; e += 256){
        int oo = e>>5, li = e&31;
        f[((size_t)(b*64+oo))*Ll + l0+li] = so[oo][li];
    }
}

// -------------------- patch embed 1x1 conv (reads f), writes (b,l,64) --------------------
__global__ void k_patch(const float* __restrict__ f, const float* __restrict__ pw,
                        float* __restrict__ out){
    __shared__ float sx[64][33];
    __shared__ float so[64][33];
    int b = blockIdx.y; int l0 = blockIdx.x*32;
    int tid = threadIdx.x;
    for (int e = tid; e < 64*32; e += 256){
        int c = e>>5, li = e&31;
        sx[c][li] = f[((size_t)(b*64+c))*Ll + l0+li];
    }
    __syncthreads();
    int o = tid>>2, lb = (tid&3)*8;
    float acc[8] = {0.f,0.f,0.f,0.f,0.f,0.f,0.f,0.f};
    for (int c = 0; c < 64; c++){
        float w = __ldg(pw + o*64 + c);
        #pragma unroll
        for (int j = 0; j < 8; j++) acc[j] += w*sx[c][lb+j];
    }
    #pragma unroll
    for (int j = 0; j < 8; j++) so[o][lb+j] = acc[j];
    __syncthreads();
    for (int e = tid; e < 64*32; e += 256){
        int o2 = e&63, li = e>>6;
        out[((size_t)(b*Ll) + l0 + li)*64 + o2] = so[o2][li];
    }
}

// -------------------- LayerNorm over last dim of 64; 4 rows per block --------------------
__global__ void k_ln64(const float* __restrict__ in, float* __restrict__ out,
                       const float* __restrict__ g, const float* __restrict__ bb){
    int tid = threadIdx.x;
    int sub = tid>>6;          // 0..3 (row within block)
    int t   = tid&63;
    size_t row = (size_t)blockIdx.x*4 + sub;
    float v = in[row*64 + t];
    float s = v, s2 = v*v;
    #pragma unroll
    for (int o = 16; o; o >>= 1){ s += __shfl_xor_sync(~0u, s, o); s2 += __shfl_xor_sync(~0u, s2, o); }
    __shared__ float sh[4][4];
    int half = t>>5;
    if ((t&31) == 0){ sh[sub][half] = s; sh[sub][2+half] = s2; }
    __syncthreads();
    float mean = (sh[sub][0]+sh[sub][1])*(1.f/64.f);
    float m2   = (sh[sub][2]+sh[sub][3])*(1.f/64.f);
    float rstd = rsqrtf(m2 - mean*mean + 1e-5f);
    out[row*64 + t] = (v-mean)*rstd*g[t] + bb[t];
}

// -------------------- generic tiled GEMM: C[M,N] (+)= act(A[M,K] @ W[N,K]^T + bias) ------
__global__ void k_gemm(const float* __restrict__ A, const float* __restrict__ Wm,
                       const float* __restrict__ bias, float* __restrict__ C,
                       int M, int Nq, int Kd, int act, int accum){
    __shared__ float As[16][68];
    __shared__ float Ws[16][68];
    int m0 = blockIdx.y<<6, n0 = blockIdx.x<<6;
    int tid = threadIdx.x;
    int tm = tid>>4, tn = tid&15;
    int lr = tid>>2, lc = (tid&3)<<2;
    float acc[4][4] = {};
    for (int kk = 0; kk < Kd; kk += 16){
        float4 av = *(const float4*)(A  + (size_t)(m0+lr)*Kd + kk + lc);
        float4 wv = *(const float4*)(Wm + (size_t)(n0+lr)*Kd + kk + lc);
        As[lc+0][lr]=av.x; As[lc+1][lr]=av.y; As[lc+2][lr]=av.z; As[lc+3][lr]=av.w;
        Ws[lc+0][lr]=wv.x; Ws[lc+1][lr]=wv.y; Ws[lc+2][lr]=wv.z; Ws[lc+3][lr]=wv.w;
        __syncthreads();
        #pragma unroll
        for (int k = 0; k < 16; k++){
            float a0=As[k][tm*4+0], a1=As[k][tm*4+1], a2=As[k][tm*4+2], a3=As[k][tm*4+3];
            float w0=Ws[k][tn*4+0], w1=Ws[k][tn*4+1], w2=Ws[k][tn*4+2], w3=Ws[k][tn*4+3];
            acc[0][0]+=a0*w0; acc[0][1]+=a0*w1; acc[0][2]+=a0*w2; acc[0][3]+=a0*w3;
            acc[1][0]+=a1*w0; acc[1][1]+=a1*w1; acc[1][2]+=a1*w2; acc[1][3]+=a1*w3;
            acc[2][0]+=a2*w0; acc[2][1]+=a2*w1; acc[2][2]+=a2*w2; acc[2][3]+=a2*w3;
            acc[3][0]+=a3*w0; acc[3][1]+=a3*w1; acc[3][2]+=a3*w2; acc[3][3]+=a3*w3;
        }
        __syncthreads();
    }
    float bv[4] = {0.f,0.f,0.f,0.f};
    if (bias){
        #pragma unroll
        for (int j = 0; j < 4; j++) bv[j] = bias[n0 + tn*4 + j];
    }
    #pragma unroll
    for (int i2 = 0; i2 < 4; i2++){
        int m = m0 + tm*4 + i2;
        float4* p = (float4*)(C + (size_t)m*Nq + n0 + tn*4);
        float v0 = acc[i2][0]+bv[0], v1 = acc[i2][1]+bv[1], v2 = acc[i2][2]+bv[2], v3 = acc[i2][3]+bv[3];
        if (act == 1){ v0=geluf(v0); v1=geluf(v1); v2=geluf(v2); v3=geluf(v3); }
        float4 ov;
        if (accum){ float4 old = *p; ov.x=old.x+v0; ov.y=old.y+v1; ov.z=old.z+v2; ov.w=old.w+v3; }
        else      { ov.x=v0; ov.y=v1; ov.z=v2; ov.w=v3; }
        *p = ov;
    }
}

// -------------------- depthwise 3x3 conv + bias + SiLU: (b,l,256)[:128] -> (b,l,d) -------
__global__ void k_dwconv(const float* __restrict__ xz, const float* __restrict__ cw,
                         const float* __restrict__ cb, float* __restrict__ xcT){
    int b = blockIdx.z, h = blockIdx.y, w0 = blockIdx.x<<5;
    int d = threadIdx.x;
    float wt[9];
    #pragma unroll
    for (int t2 = 0; t2 < 9; t2++) wt[t2] = __ldg(cw + d*9 + t2);
    float bi = __ldg(cb + d);
    for (int w = 0; w < 32; w++){
        float acc = bi;
        #pragma unroll
        for (int kh = 0; kh < 3; kh++){
            int hh = h + kh - 1;
            if ((unsigned)hh < 128u){
                #pragma unroll
                for (int kw = 0; kw < 3; kw++){
                    int ww = w0 + w + kw - 1;
                    if ((unsigned)ww < 128u)
                        acc += wt[kh*3+kw]*__ldg(xz + ((size_t)(b*Ll + hh*128 + ww))*256 + d);
                }
            }
        }
        acc = acc/(1.f + expf(-acc));   // SiLU
        xcT[((size_t)(b*Ll + h*128 + w0 + w))*128 + d] = acc;
    }
}

// -------------------- build wh-order copy: u1t[(b, w*128+h, d)] = xcT[(b, h*128+w, d)] ----
__global__ void k_transp2(const float* __restrict__ xcT, float* __restrict__ u1t){
    int b = blockIdx.y;
    int lp = blockIdx.x*2 + (threadIdx.x>>7);
    int d  = threadIdx.x & 127;
    int w = lp>>7, h = lp&127;
    u1t[((size_t)b*Ll + lp)*128 + d] = xcT[((size_t)b*Ll + h*128 + w)*128 + d];
}

// -------------------- x_proj + dt_proj + softplus, produces BC and delta (b,k,l,d) -------
__global__ void k_xproj(const float* __restrict__ xcT, const float* __restrict__ u1t,
                        const float* __restrict__ xpw, const float* __restrict__ dtw,
                        const float* __restrict__ dtb, float* __restrict__ bcbuf,
                        float* __restrict__ deltabuf){
    int k = blockIdx.y, b = blockIdx.z; int l0 = blockIdx.x*32;
    __shared__ float Us[128][33];
    __shared__ float Wp[36][128];
    __shared__ float xds[36][33];
    __shared__ float dtws[128][5];
    __shared__ float dtbs[128];
    int tid = threadIdx.x;
    const float* uptr = ((k&1) ? u1t : xcT) + (size_t)b*Ll*128;
    bool rev = (k >= 2);
    for (int e = tid; e < 128*32; e += 256){
        int d = e&127, lo = e>>7;
        int pos = l0 + lo; int src = rev ? (Ll-1-pos) : pos;
        Us[d][lo] = uptr[(size_t)src*128 + d];
    }
    for (int e = tid; e < 36*128; e += 256) Wp[e>>7][e&127] = xpw[(size_t)k*36*128 + e];
    for (int e = tid; e < 512; e += 256) dtws[e>>2][e&3] = dtw[(size_t)k*512 + e];
    if (tid < 128) dtbs[tid] = dtb[k*128 + tid];
    __syncthreads();
    for (int e = tid; e < 36*32; e += 256){
        int c = e>>5, lo = e&31;
        float acc = 0.f;
        #pragma unroll 8
        for (int d = 0; d < 128; d++) acc += Wp[c][d]*Us[d][lo];
        xds[c][lo] = acc;
    }
    __syncthreads();
    size_t bcbase = ((size_t)(b*4+k)*Ll + l0)*32;
    for (int e = tid; e < 32*32; e += 256){
        int lo = e>>5, n = e&31;
        bcbuf[bcbase + (size_t)lo*32 + n] = xds[4+n][lo];
    }
    size_t dbase = ((size_t)(b*4+k)*Ll + l0)*128;
    for (int e = tid; e < 128*32; e += 256){
        int d = e&127, lo = e>>7;
        float v = dtbs[d];
        #pragma unroll
        for (int r = 0; r < 4; r++) v += dtws[d][r]*xds[r][lo];
        v = (v > 20.f) ? v : log1pf(expf(v));   // softplus
        deltabuf[dbase + (size_t)lo*128 + d] = v;
    }
}

// -------------------- scan pass 1: per-chunk local scan (h0=0), emit P & hEnd ------------
__global__ void k_scan1(const float* __restrict__ xcT, const float* __restrict__ u1t,
                        const float* __restrict__ deltaB, const float* __restrict__ bc,
                        const float* __restrict__ Alogs, float* __restrict__ sum){
    int chunk = blockIdx.x, k = blockIdx.y, b = blockIdx.z;
    int d = threadIdx.x;
    __shared__ float sB[LC*16];
    int l0 = chunk*LC;
    const float4* bcp4 = (const float4*)(bc + ((size_t)(b*4+k)*Ll + l0)*32);
    for (int e = d; e < LC*4; e += 128){
        int t = e>>2, q = e&3;
        ((float4*)sB)[e] = bcp4[t*8 + q];
    }
    __syncthreads();
    float Ahat[16];
    const float* Ap = Alogs + (size_t)(k*128+d)*16;
    #pragma unroll
    for (int n = 0; n < 16; n++) Ahat[n] = -expf(Ap[n]);
    float h[16], P[16];
    #pragma unroll
    for (int n = 0; n < 16; n++){ h[n] = 0.f; P[n] = 1.f; }
    const float* dl = deltaB + ((size_t)(b*4+k)*Ll + l0)*128 + d;
    const float* ub = ((k&1) ? u1t : xcT) + (size_t)b*Ll*128 + d;
    bool rev = (k >= 2);
    #pragma unroll 2
    for (int t = 0; t < LC; t++){
        float dv = dl[(size_t)t*128];
        int l = l0 + t; int ls = rev ? (Ll-1-l) : l;
        float uv = ub[(size_t)ls*128];
        float du = dv*uv;
        float bb[16];
        *(float4*)(bb+0)  = *(const float4*)(sB + t*16 + 0);
        *(float4*)(bb+4)  = *(const float4*)(sB + t*16 + 4);
        *(float4*)(bb+8)  = *(const float4*)(sB + t*16 + 8);
        *(float4*)(bb+12) = *(const float4*)(sB + t*16 + 12);
        #pragma unroll
        for (int n = 0; n < 16; n++){
            float a = __expf(dv*Ahat[n]);
            P[n] *= a;
            h[n] = fmaf(a, h[n], du*bb[n]);
        }
    }
    float* sp = sum + (((size_t)((b*4+k)*NC + chunk)*128 + d)*32);
    #pragma unroll
    for (int n = 0; n < 16; n++){ sp[n] = P[n]; sp[16+n] = h[n]; }
}

// -------------------- scan pass 2: sequential combine of chunk summaries -----------------
__global__ void k_scan2(const float* __restrict__ sum, float* __restrict__ hinit){
    int tid = blockIdx.x*256 + threadIdx.x;   // 16384 threads: (kb, d, n)
    int n = tid & 15;
    int d = (tid>>4) & 127;
    int kb = tid>>11;
    float h = 0.f;
    for (int c = 0; c < NC; c++){
        size_t base = ((size_t)(kb*NC + c)*128 + d)*32;
        hinit[((size_t)(kb*NC + c)*128 + d)*16 + n] = h;
        float Pv = sum[base + n];
        float hE = sum[base + 16 + n];
        h = Pv*h + hE;
    }
}

// -------------------- scan pass 3: full scan per chunk with true init, emit y ------------
__global__ void k_scan3(const float* __restrict__ xcT, const float* __restrict__ u1t,
                        const float* __restrict__ deltaB, const float* __restrict__ bc,
                        const float* __restrict__ Alogs, const float* __restrict__ Ds,
                        const float* __restrict__ hinit, float* __restrict__ ys){
    int chunk = blockIdx.x, k = blockIdx.y, b = blockIdx.z;
    int d = threadIdx.x;
    __shared__ float sBC[LC*32];
    int l0 = chunk*LC;
    const float4* bcp4 = (const float4*)(bc + ((size_t)(b*4+k)*Ll + l0)*32);
    for (int e = d; e < LC*8; e += 128) ((float4*)sBC)[e] = bcp4[e];
    __syncthreads();
    float Ahat[16];
    const float* Ap = Alogs + (size_t)(k*128+d)*16;
    #pragma unroll
    for (int n = 0; n < 16; n++) Ahat[n] = -expf(Ap[n]);
    float Dv = Ds[k*128 + d];
    float h[16];
    const float* hi = hinit + ((size_t)((b*4+k)*NC + chunk)*128 + d)*16;
    #pragma unroll
    for (int n = 0; n < 16; n++) h[n] = hi[n];
    const float* dl = deltaB + ((size_t)(b*4+k)*Ll + l0)*128 + d;
    const float* ub = ((k&1) ? u1t : xcT) + (size_t)b*Ll*128 + d;
    float* yp = ys + ((size_t)(b*4+k)*Ll + l0)*128 + d;
    bool rev = (k >= 2);
    #pragma unroll 2
    for (int t = 0; t < LC; t++){
        float dv = dl[(size_t)t*128];
        int l = l0 + t; int ls = rev ? (Ll-1-l) : l;
        float uv = ub[(size_t)ls*128];
        float du = dv*uv;
        float bb[16], cc[16];
        const float4* rb = (const float4*)(sBC + t*32);
        *(float4*)(bb+0)=rb[0]; *(float4*)(bb+4)=rb[1]; *(float4*)(bb+8)=rb[2]; *(float4*)(bb+12)=rb[3];
        *(float4*)(cc+0)=rb[4]; *(float4*)(cc+4)=rb[5]; *(float4*)(cc+8)=rb[6]; *(float4*)(cc+12)=rb[7];
        float a0 = 0.f, a1 = 0.f, a2 = 0.f, a3 = 0.f;
        #pragma unroll
        for (int n = 0; n < 16; n += 4){
            float e0 = __expf(dv*Ahat[n+0]);
            float e1 = __expf(dv*Ahat[n+1]);
            float e2 = __expf(dv*Ahat[n+2]);
            float e3 = __expf(dv*Ahat[n+3]);
            h[n+0] = fmaf(e0, h[n+0], du*bb[n+0]);
            h[n+1] = fmaf(e1, h[n+1], du*bb[n+1]);
            h[n+2] = fmaf(e2, h[n+2], du*bb[n+2]);
            h[n+3] = fmaf(e3, h[n+3], du*bb[n+3]);
            a0 = fmaf(h[n+0], cc[n+0], a0);
            a1 = fmaf(h[n+1], cc[n+1], a1);
            a2 = fmaf(h[n+2], cc[n+2], a2);
            a3 = fmaf(h[n+3], cc[n+3], a3);
        }
        yp[(size_t)t*128] = (a0+a1)+(a2+a3) + Dv*uv;
    }
}

// -------------------- cross-merge of the 4 scan directions, (b,k,l,d) -> (b,l,d) ---------
__global__ void k_merge(const float* __restrict__ ys, float* __restrict__ ym){
    int idx = blockIdx.x*256 + threadIdx.x;
    int d = idx & 127;
    int l = (idx>>7) & 16383;
    int b = idx>>21;
    int lT = ((l & 127) << 7) | (l >> 7);
    size_t st = (size_t)Ll*128;
    size_t base = (size_t)b*4*st;
    float v = ys[base            + (size_t)l*128        + d]
            + ys[base + 2*st     + (size_t)(Ll-1-l)*128  + d]
            + ys[base + 1*st     + (size_t)lT*128        + d]
            + ys[base + 3*st     + (size_t)(Ll-1-lT)*128 + d];
    ym[((size_t)b*Ll + l)*128 + d] = v;
}

// -------------------- out_norm(LN over 128) * silu(z) --------------------
__global__ void k_yo(const float* __restrict__ ym, const float* __restrict__ xz,
                     const float* __restrict__ g, const float* __restrict__ bb,
                     float* __restrict__ yo){
    int l = blockIdx.x, b = blockIdx.y, d = threadIdx.x;
    float v = ym[((size_t)b*Ll + l)*128 + d];
    float s = v, s2 = v*v;
    #pragma unroll
    for (int o = 16; o; o >>= 1){ s += __shfl_xor_sync(~0u, s, o); s2 += __shfl_xor_sync(~0u, s2, o); }
    __shared__ float sh[8];
    if ((d&31) == 0){ sh[d>>5] = s; sh[4+(d>>5)] = s2; }
    __syncthreads();
    float mean = (sh[0]+sh[1]+sh[2]+sh[3])*(1.f/128.f);
    float m2   = (sh[4]+sh[5]+sh[6]+sh[7])*(1.f/128.f);
    float rstd = rsqrtf(m2 - mean*mean + 1e-5f);
    float z = xz[((size_t)(b*Ll) + l)*256 + 128 + d];
    float sz = z/(1.f + expf(-z));
    yo[((size_t)(b*Ll) + l)*128 + d] = ((v-mean)*rstd*g[d] + bb[d])*sz;
}

// -------------------- head conv1: 64->32, 3x3, leaky --------------------
__global__ void k_conv1(const float* __restrict__ t, const float* __restrict__ w1,
                        float* __restrict__ o1){
    int b = blockIdx.z, h = blockIdx.y, w0 = blockIdx.x<<5;
    __shared__ float st[3*34*65];
    int tid = threadIdx.x;
    for (int e = tid; e < 3*34*64; e += 256){
        int c = e & 63;
        int wi = (e>>6) % 34;
        int r  = (e>>6) / 34;
        int hh = h + r - 1, ww = w0 + wi - 1;
        float v = 0.f;
        if ((unsigned)hh < 128u && (unsigned)ww < 128u)
            v = t[((size_t)(b*Ll) + hh*128 + ww)*64 + c];
        st[(r*34 + wi)*65 + c] = v;
    }
    __syncthreads();
    int w = tid & 31, og = tid>>5;
    float acc[4] = {0.f,0.f,0.f,0.f};
    for (int kh = 0; kh < 3; kh++)
        for (int kw = 0; kw < 3; kw++){
            const float* sp = st + (kh*34 + (w+kw))*65;
            for (int ic = 0; ic < 64; ic++){
                float v = sp[ic];
                #pragma unroll
                for (int j = 0; j < 4; j++)
                    acc[j] += __ldg(w1 + ((size_t)((og*4+j)*64 + ic))*9 + kh*3 + kw)*v;
            }
        }
    #pragma unroll
    for (int j = 0; j < 4; j++){
        float v = acc[j];
        v = (v >= 0.f) ? v : 0.01f*v;
        o1[((size_t)(b*32 + og*4 + j))*Ll + h*128 + w0 + w] = v;
    }
}

// -------------------- head conv2: 32->1, 3x3, + img, sigmoid --------------------
__global__ void k_conv2(const float* __restrict__ o1, const float* __restrict__ w2,
                        const float* __restrict__ img, float* __restrict__ out){
    int idx = blockIdx.x*256 + threadIdx.x;
    int b = idx>>14, l = idx & 16383, h = l>>7, w = l & 127;
    float acc = 0.f;
    for (int ic = 0; ic < 32; ic++){
        const float* base = o1 + (size_t)(b*32 + ic)*Ll;
        #pragma unroll
        for (int kh = 0; kh < 3; kh++){
            int hh = h + kh - 1; if ((unsigned)hh >= 128u) continue;
            #pragma unroll
            for (int kw = 0; kw < 3; kw++){
                int ww = w + kw - 1; if ((unsigned)ww >= 128u) continue;
                acc += __ldg(w2 + ic*9 + kh*3 + kw)*__ldg(base + hh*128 + ww);
            }
        }
    }
    float o = acc + img[idx];
    out[idx] = 1.f/(1.f + expf(-o));
}

// -------------------- launch --------------------
extern "C" void kernel_launch(void* const* d_in, const int* in_sizes, int n_in,
                              void* d_out, int out_size){
    const float* inp_img   = (const float*)d_in[0];
    const float* x         = (const float*)d_in[1];
    const float* y         = (const float*)d_in[2];
    const float* reduce_w  = (const float*)d_in[3];
    const float* patch_w   = (const float*)d_in[4];
    const float* patch_g   = (const float*)d_in[5];
    const float* patch_b   = (const float*)d_in[6];
    const float* ln1_g     = (const float*)d_in[7];
    const float* ln1_b     = (const float*)d_in[8];
    const float* in_proj_w = (const float*)d_in[9];
    const float* conv_w    = (const float*)d_in[10];
    const float* conv_b    = (const float*)d_in[11];
    const float* x_proj_w  = (const float*)d_in[12];
    const float* dt_proj_w = (const float*)d_in[13];
    const float* dt_proj_b = (const float*)d_in[14];
    const float* A_logs    = (const float*)d_in[15];
    const float* Ds_p      = (const float*)d_in[16];
    const float* out_norm_g= (const float*)d_in[17];
    const float* out_norm_b= (const float*)d_in[18];
    const float* out_proj_w= (const float*)d_in[19];
    const float* ln2_g     = (const float*)d_in[20];
    const float* ln2_b     = (const float*)d_in[21];
    const float* fc1_w     = (const float*)d_in[22];
    const float* fc1_b     = (const float*)d_in[23];
    const float* fc2_w     = (const float*)d_in[24];
    const float* fc2_b     = (const float*)d_in[25];
    const float* out1_w    = (const float*)d_in[26];
    const float* out2_w    = (const float*)d_in[27];

    float* out = (float*)d_out;
    float* f   = out + Bn*Ll;   // second output: f at offset 32768

    float *t, *h, *xz, *xcT, *u1t, *bcp, *delta, *ysb, *ymb, *yob, *o1b, *sumb, *hib;
    cudaGetSymbolAddress((void**)&t,    g_t);
    cudaGetSymbolAddress((void**)&h,    g_h);
    cudaGetSymbolAddress((void**)&xz,   g_xz);
    cudaGetSymbolAddress((void**)&xcT,  g_xcT);
    cudaGetSymbolAddress((void**)&u1t,  g_u1t);
    cudaGetSymbolAddress((void**)&bcp,  g_bc);
    cudaGetSymbolAddress((void**)&delta,g_delta);
    cudaGetSymbolAddress((void**)&ysb,  g_ys);
    cudaGetSymbolAddress((void**)&ymb,  g_ym);
    cudaGetSymbolAddress((void**)&yob,  g_yo);
    cudaGetSymbolAddress((void**)&o1b,  g_o1);
    cudaGetSymbolAddress((void**)&sumb, g_sum);
    cudaGetSymbolAddress((void**)&hib,  g_hinit);

    const int M = Bn*Ll;  // 32768

    k_reduce<<<dim3(512,2), 256>>>(x, y, reduce_w, f);
    k_patch <<<dim3(512,2), 256>>>(f, patch_w, h);
    k_ln64  <<<M/4, 256>>>(h, t, patch_g, patch_b);

    for (int i = 0; i < NB; i++){
        k_ln64  <<<M/4, 256>>>(t, h, ln1_g + i*64, ln1_b + i*64);
        k_gemm  <<<dim3(4,512), 256>>>(h, in_proj_w + (size_t)i*256*64, nullptr, xz,
                                       M, 256, 64, 0, 0);
        k_dwconv<<<dim3(4,128,2), 128>>>(xz, conv_w + (size_t)i*DI*9, conv_b + i*DI, xcT);
        k_transp2<<<dim3(8192,2), 256>>>(xcT, u1t);
        k_xproj <<<dim3(512,4,2), 256>>>(xcT, u1t,
                                         x_proj_w  + (size_t)i*Kk*36*DI,
                                         dt_proj_w + (size_t)i*Kk*DI*4,
                                         dt_proj_b + (size_t)i*Kk*DI,
                                         bcp, delta);
        k_scan1 <<<dim3(NC,Kk,Bn), 128>>>(xcT, u1t, delta, bcp,
                                          A_logs + (size_t)i*Kk*DI*16, sumb);
        k_scan2 <<<64, 256>>>(sumb, hib);
        k_scan3 <<<dim3(NC,Kk,Bn), 128>>>(xcT, u1t, delta, bcp,
                                          A_logs + (size_t)i*Kk*DI*16,
                                          Ds_p   + (size_t)i*Kk*DI, hib, ysb);
        k_merge <<<16384, 256>>>(ysb, ymb);
        k_yo    <<<dim3(Ll,Bn), 128>>>(ymb, xz, out_norm_g + i*128, out_norm_b + i*128, yob);
        k_gemm  <<<dim3(1,512), 256>>>(yob, out_proj_w + (size_t)i*64*128, nullptr, t,
                                       M, 64, 128, 0, 1);
        k_ln64  <<<M/4, 256>>>(t, h, ln2_g + i*64, ln2_b + i*64);
        k_gemm  <<<dim3(4,512), 256>>>(h, fc1_w + (size_t)i*256*64, fc1_b + i*256, xz,
                                       M, 256, 64, 1, 0);
        k_gemm  <<<dim3(1,512), 256>>>(xz, fc2_w + (size_t)i*64*256, fc2_b + i*64, t,
                                       M, 64, 256, 0, 1);
    }

    k_conv1<<<dim3(4,128,2), 256>>>(t, out1_w, o1b);
    k_conv2<<<128, 256>>>(o1b, out2_w, inp_img, out);
}

// round 4
// speedup vs baseline: 7.5930x; 1.3966x over previous
#include <cuda_runtime.h>
#include <math.h>

#define Bn 2
#define Ll 16384
#define DI 128
#define Kk 4
#define NB 4
#define NC 128          // chunks per sequence
#define LC 128          // chunk length

// -------------------- scratch (device globals; no allocation) --------------------
__device__ float g_t  [Bn*Ll*64];        // residual stream (b,l,64)
__device__ float g_h  [Bn*Ll*64];        // LN scratch (b,l,64)
__device__ float g_xz [Bn*Ll*256];       // in_proj out / MLP hidden (b,l,256)
__device__ float g_xcT[Bn*Ll*DI];        // conv+silu out, NHWC (b,l,d)
__device__ float g_u1t[Bn*Ll*DI];        // wh-order (b, w*128+h, d)
__device__ float g_bc [Bn*Kk*Ll*32];     // B(16)+C(16) per (b,k,l)
__device__ float g_delta[Bn*Kk*Ll*DI];   // (b,k,l,d)
__device__ float g_ys   [(size_t)Bn*Kk*Ll*DI];   // (b,k,l,d)
__device__ float g_yo [Bn*Ll*DI];        // gated+LN (b,l,d)
__device__ float g_o1 [Bn*32*Ll];        // head conv1 out (b,32,l)
__device__ float g_sum  [Bn*Kk*NC*DI*32];  // per-chunk {P[16], hEnd[16]}
__device__ float g_hinit[Bn*Kk*NC*DI*16];  // per-chunk init state

__device__ __forceinline__ float geluf(float v){
    return 0.5f*v*(1.f + erff(v*0.70710678118654752f));
}

// -------------------- stem: f = 1x1 conv over concat(x,y) --------------------
__global__ void k_reduce(const float* __restrict__ x, const float* __restrict__ y,
                         const float* __restrict__ rw, float* __restrict__ f){
    __shared__ float sx[128][33];
    __shared__ float so[64][33];
    int b = blockIdx.y; int l0 = blockIdx.x*32;
    int tid = threadIdx.x;
    for (int e = tid; e < 128*32; e += 256){
        int c = e>>5, li = e&31;
        sx[c][li] = (c < 64) ? x[((size_t)(b*64+c))*Ll + l0+li]
                             : y[((size_t)(b*64+c-64))*Ll + l0+li];
    }
    __syncthreads();
    int o = tid>>2, lb = (tid&3)*8;
    float acc[8] = {0.f,0.f,0.f,0.f,0.f,0.f,0.f,0.f};
    for (int c = 0; c < 128; c++){
        float w = __ldg(rw + o*128 + c);
        #pragma unroll
        for (int j = 0; j < 8; j++) acc[j] += w*sx[c][lb+j];
    }
    #pragma unroll
    for (int j = 0; j < 8; j++) so[o][lb+j] = acc[j];
    __syncthreads();
    for (int e = tid; e < 64*32; e += 256){
        int oo = e>>5, li = e&31;
        f[((size_t)(b*64+oo))*Ll + l0+li] = so[oo][li];
    }
}

// -------------------- patch embed 1x1 conv (reads f), writes (b,l,64) --------------------
__global__ void k_patch(const float* __restrict__ f, const float* __restrict__ pw,
                        float* __restrict__ out){
    __shared__ float sx[64][33];
    __shared__ float so[64][33];
    int b = blockIdx.y; int l0 = blockIdx.x*32;
    int tid = threadIdx.x;
    for (int e = tid; e < 64*32; e += 256){
        int c = e>>5, li = e&31;
        sx[c][li] = f[((size_t)(b*64+c))*Ll + l0+li];
    }
    __syncthreads();
    int o = tid>>2, lb = (tid&3)*8;
    float acc[8] = {0.f,0.f,0.f,0.f,0.f,0.f,0.f,0.f};
    for (int c = 0; c < 64; c++){
        float w = __ldg(pw + o*64 + c);
        #pragma unroll
        for (int j = 0; j < 8; j++) acc[j] += w*sx[c][lb+j];
    }
    #pragma unroll
    for (int j = 0; j < 8; j++) so[o][lb+j] = acc[j];
    __syncthreads();
    for (int e = tid; e < 64*32; e += 256){
        int o2 = e&63, li = e>>6;
        out[((size_t)(b*Ll) + l0 + li)*64 + o2] = so[o2][li];
    }
}

// -------------------- LayerNorm over last dim of 64; 4 rows per block --------------------
__global__ void k_ln64(const float* __restrict__ in, float* __restrict__ out,
                       const float* __restrict__ g, const float* __restrict__ bb){
    int tid = threadIdx.x;
    int sub = tid>>6;
    int t   = tid&63;
    size_t row = (size_t)blockIdx.x*4 + sub;
    float v = in[row*64 + t];
    float s = v, s2 = v*v;
    #pragma unroll
    for (int o = 16; o; o >>= 1){ s += __shfl_xor_sync(~0u, s, o); s2 += __shfl_xor_sync(~0u, s2, o); }
    __shared__ float sh[4][4];
    int half = t>>5;
    if ((t&31) == 0){ sh[sub][half] = s; sh[sub][2+half] = s2; }
    __syncthreads();
    float mean = (sh[sub][0]+sh[sub][1])*(1.f/64.f);
    float m2   = (sh[sub][2]+sh[sub][3])*(1.f/64.f);
    float rstd = rsqrtf(m2 - mean*mean + 1e-5f);
    out[row*64 + t] = (v-mean)*rstd*g[t] + bb[t];
}

// ------------- GEMM: 128x64 tile, 8x4 per thread. C[M,N] (+)= act(A@W^T + bias) ----------
__global__ void k_gemm(const float* __restrict__ A, const float* __restrict__ Wm,
                       const float* __restrict__ bias, float* __restrict__ C,
                       int M, int Nq, int Kd, int act, int accum){
    __shared__ float As[16][132];
    __shared__ float Ws[16][68];
    int m0 = blockIdx.y<<7, n0 = blockIdx.x<<6;
    int tid = threadIdx.x;
    int tm = tid>>4, tn = tid&15;     // tm: 16 row-groups of 8, tn: 16 col-groups of 4
    float acc[8][4] = {};
    for (int kk = 0; kk < Kd; kk += 16){
        // load A tile 128x16
        #pragma unroll
        for (int rep = 0; rep < 2; rep++){
            int f4 = tid + rep*256;
            int row = f4>>2, q = f4&3;
            float4 av = *(const float4*)(A + (size_t)(m0+row)*Kd + kk + q*4);
            As[q*4+0][row]=av.x; As[q*4+1][row]=av.y; As[q*4+2][row]=av.z; As[q*4+3][row]=av.w;
        }
        // load W tile 64x16
        {
            int row = tid>>2, q = tid&3;
            float4 wv = *(const float4*)(Wm + (size_t)(n0+row)*Kd + kk + q*4);
            Ws[q*4+0][row]=wv.x; Ws[q*4+1][row]=wv.y; Ws[q*4+2][row]=wv.z; Ws[q*4+3][row]=wv.w;
        }
        __syncthreads();
        #pragma unroll
        for (int k = 0; k < 16; k++){
            float a[8], w[4];
            *(float4*)(a+0) = *(const float4*)&As[k][tm*8+0];
            *(float4*)(a+4) = *(const float4*)&As[k][tm*8+4];
            *(float4*)(w+0) = *(const float4*)&Ws[k][tn*4];
            #pragma unroll
            for (int i = 0; i < 8; i++){
                acc[i][0] = fmaf(a[i], w[0], acc[i][0]);
                acc[i][1] = fmaf(a[i], w[1], acc[i][1]);
                acc[i][2] = fmaf(a[i], w[2], acc[i][2]);
                acc[i][3] = fmaf(a[i], w[3], acc[i][3]);
            }
        }
        __syncthreads();
    }
    float bv[4] = {0.f,0.f,0.f,0.f};
    if (bias){
        #pragma unroll
        for (int j = 0; j < 4; j++) bv[j] = bias[n0 + tn*4 + j];
    }
    #pragma unroll
    for (int i = 0; i < 8; i++){
        int m = m0 + tm*8 + i;
        float4* p = (float4*)(C + (size_t)m*Nq + n0 + tn*4);
        float v0 = acc[i][0]+bv[0], v1 = acc[i][1]+bv[1], v2 = acc[i][2]+bv[2], v3 = acc[i][3]+bv[3];
        if (act == 1){ v0=geluf(v0); v1=geluf(v1); v2=geluf(v2); v3=geluf(v3); }
        float4 ov;
        if (accum){ float4 old = *p; ov.x=old.x+v0; ov.y=old.y+v1; ov.z=old.z+v2; ov.w=old.w+v3; }
        else      { ov.x=v0; ov.y=v1; ov.z=v2; ov.w=v3; }
        *p = ov;
    }
}

// ----- depthwise 3x3 conv + bias + SiLU: writes hw order (xcT) AND wh order (u1t) --------
__global__ void k_dwconv(const float* __restrict__ xz, const float* __restrict__ cw,
                         const float* __restrict__ cb, float* __restrict__ xcT,
                         float* __restrict__ u1t){
    int b = blockIdx.z, h = blockIdx.y, w0 = blockIdx.x<<5;
    int d = threadIdx.x;
    float wt[9];
    #pragma unroll
    for (int t2 = 0; t2 < 9; t2++) wt[t2] = __ldg(cw + d*9 + t2);
    float bi = __ldg(cb + d);
    for (int w = 0; w < 32; w++){
        float acc = bi;
        #pragma unroll
        for (int kh = 0; kh < 3; kh++){
            int hh = h + kh - 1;
            if ((unsigned)hh < 128u){
                #pragma unroll
                for (int kw = 0; kw < 3; kw++){
                    int ww = w0 + w + kw - 1;
                    if ((unsigned)ww < 128u)
                        acc += wt[kh*3+kw]*__ldg(xz + ((size_t)(b*Ll + hh*128 + ww))*256 + d);
                }
            }
        }
        acc = acc/(1.f + expf(-acc));   // SiLU
        xcT[((size_t)(b*Ll + h*128 + w0 + w))*128 + d] = acc;
        u1t[((size_t)(b*Ll + (w0 + w)*128 + h))*128 + d] = acc;
    }
}

// -------------------- x_proj + dt_proj + softplus (register-tiled) -----------------------
// block: 128 l x one (k,b). 128 threads: lt=tid&31 (4 l each), ct=tid>>5 (9 c each).
__global__ void k_xproj(const float* __restrict__ xcT, const float* __restrict__ u1t,
                        const float* __restrict__ xpw, const float* __restrict__ dtw,
                        const float* __restrict__ dtb, float* __restrict__ bcbuf,
                        float* __restrict__ deltabuf){
    int k = blockIdx.y, b = blockIdx.z; int l0 = blockIdx.x*128;
    __shared__ float Wp[36*128];
    __shared__ float UX[36*132];          // phase1: Us chunk [32][132]; phase2: xds [36][132]
    __shared__ float dtws[128*4];
    __shared__ float dtbs[128];
    int tid = threadIdx.x;
    const float* uptr = ((k&1) ? u1t : xcT) + (size_t)b*Ll*128;
    bool rev = (k >= 2);
    for (int e = tid; e < 36*128; e += 128) Wp[e] = xpw[(size_t)k*36*128 + e];
    for (int e = tid; e < 512; e += 128) dtws[e] = dtw[(size_t)k*512 + e];
    dtbs[tid] = dtb[k*128 + tid];

    int lt = tid & 31;     // l-group: l = lt*4 + j
    int ct = tid >> 5;     // c-group: c = ct*9 + m
    float acc[9][4] = {};

    for (int dc = 0; dc < 128; dc += 32){
        __syncthreads();
        // load Us[32][132]: Us[d][l] = u[(src l)][dc+d]; 1024 float4 / 128 threads
        #pragma unroll
        for (int rep = 0; rep < 8; rep++){
            int f4 = tid + rep*128;
            int l = f4>>3, dq = f4&7;
            int pos = l0 + l; int src = rev ? (Ll-1-pos) : pos;
            float4 uv = *(const float4*)(uptr + (size_t)src*128 + dc + dq*4);
            UX[(dq*4+0)*132 + l] = uv.x;
            UX[(dq*4+1)*132 + l] = uv.y;
            UX[(dq*4+2)*132 + l] = uv.z;
            UX[(dq*4+3)*132 + l] = uv.w;
        }
        __syncthreads();
        #pragma unroll 4
        for (int d = 0; d < 32; d++){
            float4 uv = *(const float4*)&UX[d*132 + lt*4];
            float wv[9];
            #pragma unroll
            for (int m = 0; m < 9; m++) wv[m] = Wp[(ct*9+m)*128 + dc + d];
            #pragma unroll
            for (int m = 0; m < 9; m++){
                acc[m][0] = fmaf(wv[m], uv.x, acc[m][0]);
                acc[m][1] = fmaf(wv[m], uv.y, acc[m][1]);
                acc[m][2] = fmaf(wv[m], uv.z, acc[m][2]);
                acc[m][3] = fmaf(wv[m], uv.w, acc[m][3]);
            }
        }
    }
    __syncthreads();
    // write xds[36][132] into UX
    #pragma unroll
    for (int m = 0; m < 9; m++)
        *(float4*)&UX[(ct*9+m)*132 + lt*4] = *(float4*)acc[m];
    __syncthreads();
    // emit BC: (b,k,l,32), rows 4..35 of xds
    size_t bcbase = ((size_t)(b*4+k)*Ll + l0)*32;
    for (int e = tid; e < 128*32; e += 128){
        int lo = e>>5, n = e&31;
        bcbuf[bcbase + (size_t)lo*32 + n] = UX[(4+n)*132 + lo];
    }
    // emit delta: per-thread d = tid, loop l
    size_t dbase = ((size_t)(b*4+k)*Ll + l0)*128;
    float w0 = dtws[tid*4+0], w1 = dtws[tid*4+1], w2 = dtws[tid*4+2], w3 = dtws[tid*4+3];
    float bsv = dtbs[tid];
    for (int lo = 0; lo < 128; lo++){
        float v = bsv;
        v = fmaf(w0, UX[0*132+lo], v);
        v = fmaf(w1, UX[1*132+lo], v);
        v = fmaf(w2, UX[2*132+lo], v);
        v = fmaf(w3, UX[3*132+lo], v);
        v = (v > 20.f) ? v : log1pf(__expf(v));   // softplus
        deltabuf[dbase + (size_t)lo*128 + tid] = v;
    }
}

// -------------------- scan pass 1: per-chunk local scan (h0=0), emit P & hEnd ------------
__global__ void k_scan1(const float* __restrict__ xcT, const float* __restrict__ u1t,
                        const float* __restrict__ deltaB, const float* __restrict__ bc,
                        const float* __restrict__ Alogs, float* __restrict__ sum){
    int chunk = blockIdx.x, k = blockIdx.y, b = blockIdx.z;
    int d = threadIdx.x;
    __shared__ float sB[LC*16];
    int l0 = chunk*LC;
    const float4* bcp4 = (const float4*)(bc + ((size_t)(b*4+k)*Ll + l0)*32);
    for (int e = d; e < LC*4; e += 128){
        int t = e>>2, q = e&3;
        ((float4*)sB)[e] = bcp4[t*8 + q];
    }
    __syncthreads();
    float Ahat[16];
    const float* Ap = Alogs + (size_t)(k*128+d)*16;
    #pragma unroll
    for (int n = 0; n < 16; n++) Ahat[n] = -expf(Ap[n]);
    bool geo = true;
    #pragma unroll
    for (int n = 0; n < 16; n++)
        geo = geo && (fabsf(Ahat[n] - (float)(n+1)*Ahat[0]) <= 1e-4f*fabsf(Ahat[n]));
    float h[16];
    #pragma unroll
    for (int n = 0; n < 16; n++) h[n] = 0.f;
    float S = 0.f;
    const float* dl = deltaB + ((size_t)(b*4+k)*Ll + l0)*128 + d;
    const float* ub = ((k&1) ? u1t : xcT) + (size_t)b*Ll*128 + d;
    bool rev = (k >= 2);
    if (geo){
        float A0 = Ahat[0];
        #pragma unroll 2
        for (int t = 0; t < LC; t++){
            float dv = dl[(size_t)t*128];
            int l = l0 + t; int ls = rev ? (Ll-1-l) : l;
            float uv = ub[(size_t)ls*128];
            float du = dv*uv;
            S += dv;
            float bb[16];
            *(float4*)(bb+0)  = *(const float4*)(sB + t*16 + 0);
            *(float4*)(bb+4)  = *(const float4*)(sB + t*16 + 4);
            *(float4*)(bb+8)  = *(const float4*)(sB + t*16 + 8);
            *(float4*)(bb+12) = *(const float4*)(sB + t*16 + 12);
            float p = __expf(dv*A0);
            float a = p;
            #pragma unroll
            for (int n = 0; n < 16; n++){
                h[n] = fmaf(a, h[n], du*bb[n]);
                a *= p;
            }
        }
    } else {
        #pragma unroll 2
        for (int t = 0; t < LC; t++){
            float dv = dl[(size_t)t*128];
            int l = l0 + t; int ls = rev ? (Ll-1-l) : l;
            float uv = ub[(size_t)ls*128];
            float du = dv*uv;
            S += dv;
            float bb[16];
            *(float4*)(bb+0)  = *(const float4*)(sB + t*16 + 0);
            *(float4*)(bb+4)  = *(const float4*)(sB + t*16 + 4);
            *(float4*)(bb+8)  = *(const float4*)(sB + t*16 + 8);
            *(float4*)(bb+12) = *(const float4*)(sB + t*16 + 12);
            #pragma unroll
            for (int n = 0; n < 16; n++){
                float a = __expf(dv*Ahat[n]);
                h[n] = fmaf(a, h[n], du*bb[n]);
            }
        }
    }
    float* sp = sum + (((size_t)((b*4+k)*NC + chunk)*128 + d)*32);
    #pragma unroll
    for (int n = 0; n < 16; n++){ sp[n] = __expf(S*Ahat[n]); sp[16+n] = h[n]; }
}

// -------------------- scan pass 2: sequential combine of chunk summaries -----------------
__global__ void k_scan2(const float* __restrict__ sum, float* __restrict__ hinit){
    int tid = blockIdx.x*256 + threadIdx.x;   // 16384 threads: (kb, d, n)
    int n = tid & 15;
    int d = (tid>>4) & 127;
    int kb = tid>>11;
    float h = 0.f;
    for (int c = 0; c < NC; c++){
        size_t base = ((size_t)(kb*NC + c)*128 + d)*32;
        hinit[((size_t)(kb*NC + c)*128 + d)*16 + n] = h;
        float Pv = sum[base + n];
        float hE = sum[base + 16 + n];
        h = Pv*h + hE;
    }
}

// -------------------- scan pass 3: full scan per chunk with true init, emit y ------------
__global__ void k_scan3(const float* __restrict__ xcT, const float* __restrict__ u1t,
                        const float* __restrict__ deltaB, const float* __restrict__ bc,
                        const float* __restrict__ Alogs, const float* __restrict__ Ds,
                        const float* __restrict__ hinit, float* __restrict__ ys){
    int chunk = blockIdx.x, k = blockIdx.y, b = blockIdx.z;
    int d = threadIdx.x;
    __shared__ float sBC[LC*32];
    int l0 = chunk*LC;
    const float4* bcp4 = (const float4*)(bc + ((size_t)(b*4+k)*Ll + l0)*32);
    for (int e = d; e < LC*8; e += 128) ((float4*)sBC)[e] = bcp4[e];
    __syncthreads();
    float Ahat[16];
    const float* Ap = Alogs + (size_t)(k*128+d)*16;
    #pragma unroll
    for (int n = 0; n < 16; n++) Ahat[n] = -expf(Ap[n]);
    bool geo = true;
    #pragma unroll
    for (int n = 0; n < 16; n++)
        geo = geo && (fabsf(Ahat[n] - (float)(n+1)*Ahat[0]) <= 1e-4f*fabsf(Ahat[n]));
    float Dv = Ds[k*128 + d];
    float h[16];
    const float* hi = hinit + ((size_t)((b*4+k)*NC + chunk)*128 + d)*16;
    #pragma unroll
    for (int n = 0; n < 16; n++) h[n] = hi[n];
    const float* dl = deltaB + ((size_t)(b*4+k)*Ll + l0)*128 + d;
    const float* ub = ((k&1) ? u1t : xcT) + (size_t)b*Ll*128 + d;
    float* yp = ys + ((size_t)(b*4+k)*Ll + l0)*128 + d;
    bool rev = (k >= 2);
    if (geo){
        float A0 = Ahat[0];
        #pragma unroll 2
        for (int t = 0; t < LC; t++){
            float dv = dl[(size_t)t*128];
            int l = l0 + t; int ls = rev ? (Ll-1-l) : l;
            float uv = ub[(size_t)ls*128];
            float du = dv*uv;
            float bb[16], cc[16];
            const float4* rb = (const float4*)(sBC + t*32);
            *(float4*)(bb+0)=rb[0]; *(float4*)(bb+4)=rb[1]; *(float4*)(bb+8)=rb[2]; *(float4*)(bb+12)=rb[3];
            *(float4*)(cc+0)=rb[4]; *(float4*)(cc+4)=rb[5]; *(float4*)(cc+8)=rb[6]; *(float4*)(cc+12)=rb[7];
            float p = __expf(dv*A0);
            float a = p;
            float y0 = 0.f, y1 = 0.f;
            #pragma unroll
            for (int n = 0; n < 16; n += 2){
                h[n]   = fmaf(a, h[n],   du*bb[n]);   a *= p;
                h[n+1] = fmaf(a, h[n+1], du*bb[n+1]); a *= p;
                y0 = fmaf(h[n],   cc[n],   y0);
                y1 = fmaf(h[n+1], cc[n+1], y1);
            }
            yp[(size_t)t*128] = y0 + y1 + Dv*uv;
        }
    } else {
        #pragma unroll 2
        for (int t = 0; t < LC; t++){
            float dv = dl[(size_t)t*128];
            int l = l0 + t; int ls = rev ? (Ll-1-l) : l;
            float uv = ub[(size_t)ls*128];
            float du = dv*uv;
            float bb[16], cc[16];
            const float4* rb = (const float4*)(sBC + t*32);
            *(float4*)(bb+0)=rb[0]; *(float4*)(bb+4)=rb[1]; *(float4*)(bb+8)=rb[2]; *(float4*)(bb+12)=rb[3];
            *(float4*)(cc+0)=rb[4]; *(float4*)(cc+4)=rb[5]; *(float4*)(cc+8)=rb[6]; *(float4*)(cc+12)=rb[7];
            float y0 = 0.f, y1 = 0.f;
            #pragma unroll
            for (int n = 0; n < 16; n += 2){
                float e0 = __expf(dv*Ahat[n]);
                float e1 = __expf(dv*Ahat[n+1]);
                h[n]   = fmaf(e0, h[n],   du*bb[n]);
                h[n+1] = fmaf(e1, h[n+1], du*bb[n+1]);
                y0 = fmaf(h[n],   cc[n],   y0);
                y1 = fmaf(h[n+1], cc[n+1], y1);
            }
            yp[(size_t)t*128] = y0 + y1 + Dv*uv;
        }
    }
}

// ------------- fused cross-merge + out_norm(LN 128) * silu(z) -> yo ----------------------
__global__ void k_yo(const float* __restrict__ ys, const float* __restrict__ xz,
                     const float* __restrict__ g, const float* __restrict__ bb,
                     float* __restrict__ yo){
    int l = blockIdx.x, b = blockIdx.y, d = threadIdx.x;
    int lT = ((l & 127) << 7) | (l >> 7);
    size_t st = (size_t)Ll*128;
    size_t base = (size_t)b*4*st;
    float v = ys[base        + (size_t)l*128         + d]
            + ys[base + 2*st + (size_t)(Ll-1-l)*128  + d]
            + ys[base + 1*st + (size_t)lT*128        + d]
            + ys[base + 3*st + (size_t)(Ll-1-lT)*128 + d];
    float s = v, s2 = v*v;
    #pragma unroll
    for (int o = 16; o; o >>= 1){ s += __shfl_xor_sync(~0u, s, o); s2 += __shfl_xor_sync(~0u, s2, o); }
    __shared__ float sh[8];
    if ((d&31) == 0){ sh[d>>5] = s; sh[4+(d>>5)] = s2; }
    __syncthreads();
    float mean = (sh[0]+sh[1]+sh[2]+sh[3])*(1.f/128.f);
    float m2   = (sh[4]+sh[5]+sh[6]+sh[7])*(1.f/128.f);
    float rstd = rsqrtf(m2 - mean*mean + 1e-5f);
    float z = xz[((size_t)(b*Ll) + l)*256 + 128 + d];
    float sz = z/(1.f + expf(-z));
    yo[((size_t)(b*Ll) + l)*128 + d] = ((v-mean)*rstd*g[d] + bb[d])*sz;
}

// -------------------- head conv1: 64->32, 3x3, leaky --------------------
__global__ void k_conv1(const float* __restrict__ t, const float* __restrict__ w1,
                        float* __restrict__ o1){
    int b = blockIdx.z, h = blockIdx.y, w0 = blockIdx.x<<5;
    __shared__ float st[3*34*65];
    int tid = threadIdx.x;
    for (int e = tid; e < 3*34*64; e += 256){
        int c = e & 63;
        int wi = (e>>6) % 34;
        int r  = (e>>6) / 34;
        int hh = h + r - 1, ww = w0 + wi - 1;
        float v = 0.f;
        if ((unsigned)hh < 128u && (unsigned)ww < 128u)
            v = t[((size_t)(b*Ll) + hh*128 + ww)*64 + c];
        st[(r*34 + wi)*65 + c] = v;
    }
    __syncthreads();
    int w = tid & 31, og = tid>>5;
    float acc[4] = {0.f,0.f,0.f,0.f};
    for (int kh = 0; kh < 3; kh++)
        for (int kw = 0; kw < 3; kw++){
            const float* sp = st + (kh*34 + (w+kw))*65;
            for (int ic = 0; ic < 64; ic++){
                float v = sp[ic];
                #pragma unroll
                for (int j = 0; j < 4; j++)
                    acc[j] += __ldg(w1 + ((size_t)((og*4+j)*64 + ic))*9 + kh*3 + kw)*v;
            }
        }
    #pragma unroll
    for (int j = 0; j < 4; j++){
        float v = acc[j];
        v = (v >= 0.f) ? v : 0.01f*v;
        o1[((size_t)(b*32 + og*4 + j))*Ll + h*128 + w0 + w] = v;
    }
}

// -------------------- head conv2: 32->1, 3x3, + img, sigmoid --------------------
__global__ void k_conv2(const float* __restrict__ o1, const float* __restrict__ w2,
                        const float* __restrict__ img, float* __restrict__ out){
    int idx = blockIdx.x*256 + threadIdx.x;
    int b = idx>>14, l = idx & 16383, h = l>>7, w = l & 127;
    float acc = 0.f;
    for (int ic = 0; ic < 32; ic++){
        const float* base = o1 + (size_t)(b*32 + ic)*Ll;
        #pragma unroll
        for (int kh = 0; kh < 3; kh++){
            int hh = h + kh - 1; if ((unsigned)hh >= 128u) continue;
            #pragma unroll
            for (int kw = 0; kw < 3; kw++){
                int ww = w + kw - 1; if ((unsigned)ww >= 128u) continue;
                acc += __ldg(w2 + ic*9 + kh*3 + kw)*__ldg(base + hh*128 + ww);
            }
        }
    }
    float o = acc + img[idx];
    out[idx] = 1.f/(1.f + expf(-o));
}

// -------------------- launch --------------------
extern "C" void kernel_launch(void* const* d_in, const int* in_sizes, int n_in,
                              void* d_out, int out_size){
    const float* inp_img   = (const float*)d_in[0];
    const float* x         = (const float*)d_in[1];
    const float* y         = (const float*)d_in[2];
    const float* reduce_w  = (const float*)d_in[3];
    const float* patch_w   = (const float*)d_in[4];
    const float* patch_g   = (const float*)d_in[5];
    const float* patch_b   = (const float*)d_in[6];
    const float* ln1_g     = (const float*)d_in[7];
    const float* ln1_b     = (const float*)d_in[8];
    const float* in_proj_w = (const float*)d_in[9];
    const float* conv_w    = (const float*)d_in[10];
    const float* conv_b    = (const float*)d_in[11];
    const float* x_proj_w  = (const float*)d_in[12];
    const float* dt_proj_w = (const float*)d_in[13];
    const float* dt_proj_b = (const float*)d_in[14];
    const float* A_logs    = (const float*)d_in[15];
    const float* Ds_p      = (const float*)d_in[16];
    const float* out_norm_g= (const float*)d_in[17];
    const float* out_norm_b= (const float*)d_in[18];
    const float* out_proj_w= (const float*)d_in[19];
    const float* ln2_g     = (const float*)d_in[20];
    const float* ln2_b     = (const float*)d_in[21];
    const float* fc1_w     = (const float*)d_in[22];
    const float* fc1_b     = (const float*)d_in[23];
    const float* fc2_w     = (const float*)d_in[24];
    const float* fc2_b     = (const float*)d_in[25];
    const float* out1_w    = (const float*)d_in[26];
    const float* out2_w    = (const float*)d_in[27];

    float* out = (float*)d_out;
    float* f   = out + Bn*Ll;   // second output: f at offset 32768

    float *t, *h, *xz, *xcT, *u1t, *bcp, *delta, *ysb, *yob, *o1b, *sumb, *hib;
    cudaGetSymbolAddress((void**)&t,    g_t);
    cudaGetSymbolAddress((void**)&h,    g_h);
    cudaGetSymbolAddress((void**)&xz,   g_xz);
    cudaGetSymbolAddress((void**)&xcT,  g_xcT);
    cudaGetSymbolAddress((void**)&u1t,  g_u1t);
    cudaGetSymbolAddress((void**)&bcp,  g_bc);
    cudaGetSymbolAddress((void**)&delta,g_delta);
    cudaGetSymbolAddress((void**)&ysb,  g_ys);
    cudaGetSymbolAddress((void**)&yob,  g_yo);
    cudaGetSymbolAddress((void**)&o1b,  g_o1);
    cudaGetSymbolAddress((void**)&sumb, g_sum);
    cudaGetSymbolAddress((void**)&hib,  g_hinit);

    const int M = Bn*Ll;  // 32768

    k_reduce<<<dim3(512,2), 256>>>(x, y, reduce_w, f);
    k_patch <<<dim3(512,2), 256>>>(f, patch_w, h);
    k_ln64  <<<M/4, 256>>>(h, t, patch_g, patch_b);

    for (int i = 0; i < NB; i++){
        k_ln64  <<<M/4, 256>>>(t, h, ln1_g + i*64, ln1_b + i*64);
        k_gemm  <<<dim3(4,256), 256>>>(h, in_proj_w + (size_t)i*256*64, nullptr, xz,
                                       M, 256, 64, 0, 0);
        k_dwconv<<<dim3(4,128,2), 128>>>(xz, conv_w + (size_t)i*DI*9, conv_b + i*DI, xcT, u1t);
        k_xproj <<<dim3(128,4,2), 128>>>(xcT, u1t,
                                         x_proj_w  + (size_t)i*Kk*36*DI,
                                         dt_proj_w + (size_t)i*Kk*DI*4,
                                         dt_proj_b + (size_t)i*Kk*DI,
                                         bcp, delta);
        k_scan1 <<<dim3(NC,Kk,Bn), 128>>>(xcT, u1t, delta, bcp,
                                          A_logs + (size_t)i*Kk*DI*16, sumb);
        k_scan2 <<<64, 256>>>(sumb, hib);
        k_scan3 <<<dim3(NC,Kk,Bn), 128>>>(xcT, u1t, delta, bcp,
                                          A_logs + (size_t)i*Kk*DI*16,
                                          Ds_p   + (size_t)i*Kk*DI, hib, ysb);
        k_yo    <<<dim3(Ll,Bn), 128>>>(ysb, xz, out_norm_g + i*128, out_norm_b + i*128, yob);
        k_gemm  <<<dim3(1,256), 256>>>(yob, out_proj_w + (size_t)i*64*128, nullptr, t,
                                       M, 64, 128, 0, 1);
        k_ln64  <<<M/4, 256>>>(t, h, ln2_g + i*64, ln2_b + i*64);
        k_gemm  <<<dim3(4,256), 256>>>(h, fc1_w + (size_t)i*256*64, fc1_b + i*256, xz,
                                       M, 256, 64, 1, 0);
        k_gemm  <<<dim3(1,256), 256>>>(xz, fc2_w + (size_t)i*64*256, fc2_b + i*64, t,
                                       M, 64, 256, 0, 1);
    }

    k_conv1<<<dim3(4,128,2), 256>>>(t, out1_w, o1b);
    k_conv2<<<128, 256>>>(o1b, out2_w, inp_img, out);
}